// round 1
// baseline (speedup 1.0000x reference)
#include <cuda_runtime.h>
#include <math.h>

#define TOK   2048      // B*S tokens
#define HD    512       // hidden
#define FD    2048      // ffn dim
#define NE    8         // experts
#define NSLOTS (TOK*2)  // top-2 => 4096 token-expert slots

// ---------------- device scratch (static: no allocations) ----------------
__device__ int   g_count[NE];
__device__ int   g_base[NE];
__device__ int   g_cursor[NE];
__device__ int   g_topi[TOK*2];
__device__ float g_topw[TOK*2];
__device__ int   g_perm[NSLOTS];      // slot -> token
__device__ float g_wt[NSLOTS];        // slot -> combine weight
__device__ int   g_slot_of[TOK*2];    // token,k -> slot
__device__ float g_act[(size_t)NSLOTS*FD]; // 32 MB: silu(x@W1+b1) per slot
__device__ float g_y[(size_t)NSLOTS*HD];   // 8 MB: weighted expert output per slot

// ---------------- small kernels ----------------
__global__ void zero_kernel() {
    int i = threadIdx.x;
    if (i < NE) { g_count[i] = 0; g_cursor[i] = 0; }
}

// One warp per token: 8 routed scores, top-2, renormalized weights.
__global__ void router_kernel(const float* __restrict__ x,
                              const float* __restrict__ Wg) {
    int warp = threadIdx.x >> 5;
    int lane = threadIdx.x & 31;
    int t = blockIdx.x * 8 + warp;
    if (t >= TOK) return;
    float acc[NE];
#pragma unroll
    for (int e = 0; e < NE; e++) acc[e] = 0.f;
    const float* xr = x + (size_t)t * HD;
    for (int i = lane; i < HD; i += 32) {
        float xv = xr[i];
#pragma unroll
        for (int e = 0; e < NE; e++) acc[e] += xv * Wg[e*HD + i];
    }
#pragma unroll
    for (int off = 16; off > 0; off >>= 1) {
#pragma unroll
        for (int e = 0; e < NE; e++)
            acc[e] += __shfl_xor_sync(0xffffffffu, acc[e], off);
    }
    if (lane == 0) {
        int i0 = 0;
#pragma unroll
        for (int e = 1; e < NE; e++) if (acc[e] > acc[i0]) i0 = e;
        int i1 = (i0 == 0) ? 1 : 0;
#pragma unroll
        for (int e = 0; e < NE; e++)
            if (e != i0 && acc[e] > acc[i1]) i1 = e;
        // softmax denominator cancels in renorm: w0 = e^{s0}/(e^{s0}+e^{s1})
        float m  = acc[i0];
        float e0 = expf(acc[i0] - m);
        float e1 = expf(acc[i1] - m);
        float inv = 1.f / (e0 + e1);
        g_topi[t*2+0] = i0;  g_topw[t*2+0] = e0 * inv;
        g_topi[t*2+1] = i1;  g_topw[t*2+1] = e1 * inv;
        atomicAdd(&g_count[i0], 1);
        atomicAdd(&g_count[i1], 1);
    }
}

__global__ void scan_kernel() {
    // single thread: 8-entry exclusive prefix sum
    int s = 0;
#pragma unroll
    for (int e = 0; e < NE; e++) { g_base[e] = s; s += g_count[e]; }
}

__global__ void scatter_kernel() {
    int t = blockIdx.x * 256 + threadIdx.x;
    if (t >= TOK) return;
#pragma unroll
    for (int k = 0; k < 2; k++) {
        int e = g_topi[t*2+k];
        int pos = atomicAdd(&g_cursor[e], 1);
        int slot = g_base[e] + pos;
        g_perm[slot] = t;
        g_wt[slot]   = g_topw[t*2+k];
        g_slot_of[t*2+k] = slot;
    }
}

// ---------------- grouped expert GEMM ----------------
// PASS1: C[slot, n] = silu( gatherA(x)[slot, :] @ W1_e + b1_e )  (KDIM=HD, NDIM=FD)
// PASS2: C[slot, n] = ( act[slot, :] @ W2_e + b2_e ) * wt[slot]  (KDIM=FD, NDIM=HD)
// 64x64 tile, TK=16, 256 threads, 4x4 micro-tile per thread.
template<int KDIM, int NDIM, bool PASS1>
__global__ __launch_bounds__(256)
void expert_gemm(const float* __restrict__ Xgm,   // x for PASS1, unused PASS2
                 const float* __restrict__ Bgm,   // W1 or W2, [E, KDIM, NDIM]
                 const float* __restrict__ bias)  // [E, NDIM]
{
    int e   = blockIdx.z;
    int cnt = g_count[e];
    int m0  = blockIdx.y * 64;
    if (m0 >= cnt) return;
    int n0   = blockIdx.x * 64;
    int base = g_base[e];

    const float* Agm = PASS1 ? Xgm : g_act;
    float*       Cgm = PASS1 ? g_act : g_y;
    const float* B0  = Bgm + (size_t)e * KDIM * NDIM;

    __shared__ float As[16][64];
    __shared__ float Bs[16][64];

    int tid = threadIdx.x;
    int tn = tid & 15, tm = tid >> 4;

    // A tile load mapping: thread -> (row, k-quad)
    int ar = tid >> 2;            // 0..63
    int ak = (tid & 3) * 4;       // 0,4,8,12
    int am = m0 + ar;
    int arow;
    if (PASS1) {
        int slot = base + (am < cnt ? am : 0);
        arow = g_perm[slot];      // gather token row from x
    } else {
        arow = base + (am < cnt ? am : 0);
    }
    const float* aptr = Agm + (size_t)arow * KDIM + ak;

    // B tile load mapping
    int bk = tid >> 4;            // 0..15
    int bn = (tid & 15) * 4;      // 0..60
    const float* bptr = B0 + (size_t)bk * NDIM + n0 + bn;

    float c[4][4];
#pragma unroll
    for (int i = 0; i < 4; i++)
#pragma unroll
        for (int j = 0; j < 4; j++) c[i][j] = 0.f;

    for (int k0 = 0; k0 < KDIM; k0 += 16) {
        float4 av = *(const float4*)(aptr + k0);
        float4 bv = *(const float4*)(bptr + (size_t)k0 * NDIM);
        As[ak+0][ar] = av.x; As[ak+1][ar] = av.y;
        As[ak+2][ar] = av.z; As[ak+3][ar] = av.w;
        *(float4*)&Bs[bk][bn] = bv;
        __syncthreads();
#pragma unroll
        for (int kk = 0; kk < 16; kk++) {
            float4 a4 = *(const float4*)&As[kk][tm*4];
            float4 b4 = *(const float4*)&Bs[kk][tn*4];
            float aa[4] = {a4.x, a4.y, a4.z, a4.w};
            float bb[4] = {b4.x, b4.y, b4.z, b4.w};
#pragma unroll
            for (int i = 0; i < 4; i++)
#pragma unroll
                for (int j = 0; j < 4; j++)
                    c[i][j] += aa[i] * bb[j];
        }
        __syncthreads();
    }

    // epilogue
#pragma unroll
    for (int i = 0; i < 4; i++) {
        int m = m0 + tm*4 + i;
        if (m >= cnt) continue;
        int slot = base + m;
        float scale = PASS1 ? 1.f : g_wt[slot];
#pragma unroll
        for (int j = 0; j < 4; j++) {
            int n = n0 + tn*4 + j;
            float v = c[i][j] + bias[e*NDIM + n];
            if (PASS1) v = v / (1.f + expf(-v));   // silu
            else       v *= scale;
            Cgm[(size_t)slot * NDIM + n] = v;
        }
    }
}

// out[t,h] = y[slot0][h] + y[slot1][h]   (weights already folded into y)
__global__ void combine_kernel(float* __restrict__ out) {
    int idx = blockIdx.x * 256 + threadIdx.x;   // over TOK * HD/4
    if (idx >= TOK * (HD/4)) return;
    int t  = idx / (HD/4);
    int h4 = idx % (HD/4);
    int s0 = g_slot_of[t*2+0];
    int s1 = g_slot_of[t*2+1];
    float4 a = *(const float4*)&g_y[(size_t)s0 * HD + h4*4];
    float4 b = *(const float4*)&g_y[(size_t)s1 * HD + h4*4];
    float4 o;
    o.x = a.x + b.x; o.y = a.y + b.y; o.z = a.z + b.z; o.w = a.w + b.w;
    *(float4*)&out[(size_t)t * HD + h4*4] = o;
}

// ---------------- launch ----------------
extern "C" void kernel_launch(void* const* d_in, const int* in_sizes, int n_in,
                              void* d_out, int out_size) {
    const float* x  = (const float*)d_in[0];  // [2,1024,512]
    const float* Wg = (const float*)d_in[1];  // [8,512]
    const float* W1 = (const float*)d_in[2];  // [8,512,2048]
    const float* b1 = (const float*)d_in[3];  // [8,2048]
    const float* W2 = (const float*)d_in[4];  // [8,2048,512]
    const float* b2 = (const float*)d_in[5];  // [8,512]
    float* out = (float*)d_out;               // [2,1024,512]

    zero_kernel<<<1, 32>>>();
    router_kernel<<<TOK/8, 256>>>(x, Wg);
    scan_kernel<<<1, 1>>>();
    scatter_kernel<<<TOK/256, 256>>>();

    // Pass A: [cnt_e x 512] @ [512 x 2048] -> silu -> g_act
    {
        dim3 grid(FD/64, 32, NE);   // (n-tiles, max m-tiles, experts)
        expert_gemm<HD, FD, true><<<grid, 256>>>(x, W1, b1);
    }
    // Pass B: [cnt_e x 2048] @ [2048 x 512] -> *wt -> g_y
    {
        dim3 grid(HD/64, 32, NE);
        expert_gemm<FD, HD, false><<<grid, 256>>>(nullptr, W2, b2);
    }
    combine_kernel<<<(TOK*(HD/4) + 255)/256, 256>>>(out);
}

// round 3
// speedup vs baseline: 1.7515x; 1.7515x over previous
#include <cuda_runtime.h>
#include <cuda_bf16.h>
#include <math.h>
#include <stdint.h>

#define TOK   2048
#define HD    512
#define FD    2048
#define NE    8
#define NSLOTS (TOK*2)

// ================= device scratch =================
__device__ int   g_count[NE];
__device__ int   g_base[NE];
__device__ int   g_cursor[NE];
__device__ int   g_topi[TOK*2];
__device__ float g_topw[TOK*2];
__device__ int   g_perm[NSLOTS];
__device__ float g_wt[NSLOTS];
__device__ int   g_slot_of[TOK*2];
__device__ __align__(16) uint32_t      g_act[(size_t)NSLOTS*FD];   // packed (hi | lo<<16) bf16
__device__ __align__(16) float         g_y[(size_t)NSLOTS*HD];
__device__ __align__(16) __nv_bfloat16 g_W1T_hi[(size_t)NE*FD*HD]; // [E][F][H]
__device__ __align__(16) __nv_bfloat16 g_W1T_lo[(size_t)NE*FD*HD];
__device__ __align__(16) __nv_bfloat16 g_W2T_hi[(size_t)NE*HD*FD]; // [E][H][F]
__device__ __align__(16) __nv_bfloat16 g_W2T_lo[(size_t)NE*HD*FD];

// ================= PTX helpers (portable: sm_75/80 features only) =================
__device__ __forceinline__ uint32_t smem_u32(const void* p) {
    uint32_t a;
    asm("{ .reg .u64 t; cvta.to.shared.u64 t, %1; cvt.u32.u64 %0, t; }" : "=r"(a) : "l"(p));
    return a;
}
__device__ __forceinline__ void ldm4(uint32_t* r, uint32_t addr) {
    asm volatile("ldmatrix.sync.aligned.m8n8.x4.shared.b16 {%0,%1,%2,%3}, [%4];"
        : "=r"(r[0]), "=r"(r[1]), "=r"(r[2]), "=r"(r[3]) : "r"(addr));
}
__device__ __forceinline__ void mma_bf16(float* c, const uint32_t* a, const uint32_t* b) {
    asm volatile("mma.sync.aligned.m16n8k16.row.col.f32.bf16.bf16.f32 "
        "{%0,%1,%2,%3}, {%4,%5,%6,%7}, {%8,%9}, {%0,%1,%2,%3};"
        : "+f"(c[0]), "+f"(c[1]), "+f"(c[2]), "+f"(c[3])
        : "r"(a[0]), "r"(a[1]), "r"(a[2]), "r"(a[3]), "r"(b[0]), "r"(b[1]));
}

// split 8 fp32 -> bf16 hi (uint4) + bf16 lo (uint4)
__device__ __forceinline__ void split8(const float* f, uint4& hi, uint4& lo) {
    uint32_t h[8], l[8];
#pragma unroll
    for (int i = 0; i < 8; i++) {
        __nv_bfloat16 hb = __float2bfloat16(f[i]);
        float r = f[i] - __bfloat162float(hb);
        h[i] = (uint32_t)__bfloat16_as_ushort(hb);
        l[i] = (uint32_t)__bfloat16_as_ushort(__float2bfloat16(r));
    }
    hi.x = h[0] | (h[1] << 16); hi.y = h[2] | (h[3] << 16);
    hi.z = h[4] | (h[5] << 16); hi.w = h[6] | (h[7] << 16);
    lo.x = l[0] | (l[1] << 16); lo.y = l[2] | (l[3] << 16);
    lo.z = l[4] | (l[5] << 16); lo.w = l[6] | (l[7] << 16);
}

// ================= routing =================
__global__ void zero_kernel() {
    int i = threadIdx.x;
    if (i < NE) { g_count[i] = 0; g_cursor[i] = 0; }
}

__global__ void router_kernel(const float* __restrict__ x,
                              const float* __restrict__ Wg) {
    int warp = threadIdx.x >> 5, lane = threadIdx.x & 31;
    int t = blockIdx.x * 8 + warp;
    if (t >= TOK) return;
    float acc[NE];
#pragma unroll
    for (int e = 0; e < NE; e++) acc[e] = 0.f;
    const float* xr = x + (size_t)t * HD;
    for (int i = lane; i < HD; i += 32) {
        float xv = xr[i];
#pragma unroll
        for (int e = 0; e < NE; e++) acc[e] += xv * Wg[e*HD + i];
    }
#pragma unroll
    for (int off = 16; off > 0; off >>= 1)
#pragma unroll
        for (int e = 0; e < NE; e++)
            acc[e] += __shfl_xor_sync(0xffffffffu, acc[e], off);
    if (lane == 0) {
        int i0 = 0;
#pragma unroll
        for (int e = 1; e < NE; e++) if (acc[e] > acc[i0]) i0 = e;
        int i1 = (i0 == 0) ? 1 : 0;
#pragma unroll
        for (int e = 0; e < NE; e++)
            if (e != i0 && acc[e] > acc[i1]) i1 = e;
        float e1 = expf(acc[i1] - acc[i0]);
        float inv = 1.f / (1.f + e1);
        g_topi[t*2+0] = i0; g_topw[t*2+0] = inv;
        g_topi[t*2+1] = i1; g_topw[t*2+1] = e1 * inv;
        atomicAdd(&g_count[i0], 1);
        atomicAdd(&g_count[i1], 1);
    }
}

__global__ void scan_kernel() {
    int s = 0;
#pragma unroll
    for (int e = 0; e < NE; e++) { g_base[e] = s; s += g_count[e]; }
}

__global__ void scatter_kernel() {
    int t = blockIdx.x * 256 + threadIdx.x;
    if (t >= TOK) return;
#pragma unroll
    for (int k = 0; k < 2; k++) {
        int e = g_topi[t*2+k];
        int pos = atomicAdd(&g_cursor[e], 1);
        int slot = g_base[e] + pos;
        g_perm[slot] = t;
        g_wt[slot]   = g_topw[t*2+k];
        g_slot_of[t*2+k] = slot;
    }
}

// ================= weight transpose + bf16 split =================
// W [e][K][N] fp32 -> Thi/Tlo [e][N][K] bf16
template<int K, int N>
__global__ void transpose_split(const float* __restrict__ W,
                                __nv_bfloat16* __restrict__ Thi,
                                __nv_bfloat16* __restrict__ Tlo) {
    __shared__ float tile[32][33];
    int e  = blockIdx.z;
    int n0 = blockIdx.x * 32, k0 = blockIdx.y * 32;
    const float* Wp = W + (size_t)e * K * N;
    for (int i = threadIdx.y; i < 32; i += 8)
        tile[i][threadIdx.x] = Wp[(size_t)(k0 + i) * N + n0 + threadIdx.x];
    __syncthreads();
    for (int i = threadIdx.y; i < 32; i += 8) {
        float v = tile[threadIdx.x][i];
        __nv_bfloat16 hi = __float2bfloat16(v);
        __nv_bfloat16 lo = __float2bfloat16(v - __bfloat162float(hi));
        size_t o = ((size_t)e * N + n0 + i) * K + k0 + threadIdx.x;
        Thi[o] = hi;
        Tlo[o] = lo;
    }
}

// ================= grouped GEMM on mma.sync (tensor pipe) =================
// CTA tile 128x128, K-chunk 32. 8 warps: wm = wid&3 (32 rows), wn = wid>>2 (64 cols).
// Per warp: 2 m16-tiles x 8 n8-tiles, bf16-split: hi*hi + hi*lo + lo*hi.
// PASS1: C = silu(gather(x) @ W1T + b1) -> g_act packed bf16 pairs
// PASS2: C = (act @ W2T + b2) * wt     -> g_y fp32
#define APAD 40   // bf16 elements per smem row (32 data + 8 pad): conflict-free ldmatrix

template<int KDIM, int NDIM, bool PASS1>
__global__ __launch_bounds__(256, 2)
void moe_gemm(const float* __restrict__ xsrc,
              const __nv_bfloat16* __restrict__ Whi,
              const __nv_bfloat16* __restrict__ Wlo,
              const float* __restrict__ bias) {
    __shared__ __align__(16) __nv_bfloat16 sAhi[128*APAD];
    __shared__ __align__(16) __nv_bfloat16 sAlo[128*APAD];
    __shared__ __align__(16) __nv_bfloat16 sBhi[128*APAD];
    __shared__ __align__(16) __nv_bfloat16 sBlo[128*APAD];

    int e   = blockIdx.z;
    int cnt = g_count[e];
    int m0  = blockIdx.y * 128;
    if (m0 >= cnt) return;
    int n0   = blockIdx.x * 128;
    int base = g_base[e];

    int tid = threadIdx.x, wid = tid >> 5, lane = tid & 31;
    int wm = wid & 3, wn = wid >> 2;

    uint32_t aAhi = smem_u32(sAhi), aAlo = smem_u32(sAlo);
    uint32_t aBhi = smem_u32(sBhi), aBlo = smem_u32(sBlo);

    // loader mapping: 2 threads per row; each covers 16 k-elements
    int lrow = tid >> 1;
    int lks  = (tid & 1) * 16;
    int mrow = m0 + lrow; if (mrow >= cnt) mrow = cnt - 1;
    int arow = PASS1 ? g_perm[base + mrow] : (base + mrow);
    uint32_t sA_off = (uint32_t)(lrow * APAD + lks) * 2;   // byte offset
    size_t   b_go   = ((size_t)e * NDIM + n0 + lrow) * KDIM + lks;

    float acc[2][8][4];
#pragma unroll
    for (int a = 0; a < 2; a++)
#pragma unroll
        for (int b = 0; b < 8; b++)
#pragma unroll
            for (int c = 0; c < 4; c++) acc[a][b][c] = 0.f;

    // precomputed ldmatrix lane addresses (byte offsets within tile)
    int a_r  = lane & 15, a_k = (lane >> 4) * 8;
    int b_n  = ((lane >> 4) & 1) * 8 + (lane & 7);
    int b_k  = ((lane >> 3) & 1) * 8;

    for (int k0 = 0; k0 < KDIM; k0 += 32) {
        // ---- load A chunk ----
        if (PASS1) {
            const float* src = xsrc + (size_t)arow * KDIM + k0 + lks;
            float f[8]; uint4 hi, lo;
#pragma unroll
            for (int g = 0; g < 2; g++) {
                float4 v0 = *(const float4*)(src + g*8);
                float4 v1 = *(const float4*)(src + g*8 + 4);
                f[0]=v0.x; f[1]=v0.y; f[2]=v0.z; f[3]=v0.w;
                f[4]=v1.x; f[5]=v1.y; f[6]=v1.z; f[7]=v1.w;
                split8(f, hi, lo);
                *(uint4*)((char*)sAhi + sA_off + g*16) = hi;
                *(uint4*)((char*)sAlo + sA_off + g*16) = lo;
            }
        } else {
            const uint32_t* src = g_act + (size_t)arow * KDIM + k0 + lks;
#pragma unroll
            for (int g = 0; g < 2; g++) {
                uint4 p0 = *(const uint4*)(src + g*8);
                uint4 p1 = *(const uint4*)(src + g*8 + 4);
                uint4 hi, lo;
                hi.x = (p0.x & 0xFFFFu) | (p0.y << 16);
                hi.y = (p0.z & 0xFFFFu) | (p0.w << 16);
                hi.z = (p1.x & 0xFFFFu) | (p1.y << 16);
                hi.w = (p1.z & 0xFFFFu) | (p1.w << 16);
                lo.x = (p0.x >> 16) | (p0.y & 0xFFFF0000u);
                lo.y = (p0.z >> 16) | (p0.w & 0xFFFF0000u);
                lo.z = (p1.x >> 16) | (p1.y & 0xFFFF0000u);
                lo.w = (p1.z >> 16) | (p1.w & 0xFFFF0000u);
                *(uint4*)((char*)sAhi + sA_off + g*16) = hi;
                *(uint4*)((char*)sAlo + sA_off + g*16) = lo;
            }
        }
        // ---- load B chunk (transposed weights, [n][k] rows) ----
        {
            const __nv_bfloat16* ph = Whi + b_go + k0;
            const __nv_bfloat16* pl = Wlo + b_go + k0;
            *(uint4*)((char*)sBhi + sA_off)      = *(const uint4*)(ph);
            *(uint4*)((char*)sBhi + sA_off + 16) = *(const uint4*)(ph + 8);
            *(uint4*)((char*)sBlo + sA_off)      = *(const uint4*)(pl);
            *(uint4*)((char*)sBlo + sA_off + 16) = *(const uint4*)(pl + 8);
        }
        __syncthreads();

        // ---- compute: 2 K16 steps ----
#pragma unroll
        for (int kk = 0; kk < 2; kk++) {
            uint32_t ah[2][4], al[2][4];
#pragma unroll
            for (int mt = 0; mt < 2; mt++) {
                uint32_t off = (uint32_t)((wm*32 + mt*16 + a_r) * APAD + kk*16 + a_k) * 2;
                ldm4(ah[mt], aAhi + off);
                ldm4(al[mt], aAlo + off);
            }
#pragma unroll
            for (int p = 0; p < 4; p++) {
                uint32_t off = (uint32_t)((wn*64 + p*16 + b_n) * APAD + kk*16 + b_k) * 2;
                uint32_t bh[4], bl[4];
                ldm4(bh, aBhi + off);
                ldm4(bl, aBlo + off);
#pragma unroll
                for (int mt = 0; mt < 2; mt++) {
#pragma unroll
                    for (int q = 0; q < 2; q++) {
                        float* c = acc[mt][p*2 + q];
                        mma_bf16(c, ah[mt], &bh[q*2]);
                        mma_bf16(c, ah[mt], &bl[q*2]);
                        mma_bf16(c, al[mt], &bh[q*2]);
                    }
                }
            }
        }
        __syncthreads();
    }

    // ---- epilogue ----
    int rbase = wm*32 + (lane >> 2);
    int cbase = n0 + wn*64 + (lane & 3)*2;
#pragma unroll
    for (int mt = 0; mt < 2; mt++) {
#pragma unroll
        for (int sub = 0; sub < 2; sub++) {
            int m = m0 + rbase + mt*16 + sub*8;
            if (m >= cnt) continue;
            int slot = base + m;
            float wtv = PASS1 ? 1.f : g_wt[slot];
#pragma unroll
            for (int nt = 0; nt < 8; nt++) {
                int n = cbase + nt*8;
                float v0 = acc[mt][nt][sub*2+0] + __ldg(&bias[e*NDIM + n]);
                float v1 = acc[mt][nt][sub*2+1] + __ldg(&bias[e*NDIM + n + 1]);
                if (PASS1) {
                    v0 = v0 / (1.f + __expf(-v0));
                    v1 = v1 / (1.f + __expf(-v1));
                    __nv_bfloat16 h0 = __float2bfloat16(v0);
                    __nv_bfloat16 h1 = __float2bfloat16(v1);
                    uint32_t l0 = (uint32_t)__bfloat16_as_ushort(__float2bfloat16(v0 - __bfloat162float(h0)));
                    uint32_t l1 = (uint32_t)__bfloat16_as_ushort(__float2bfloat16(v1 - __bfloat162float(h1)));
                    uint2 pk;
                    pk.x = (uint32_t)__bfloat16_as_ushort(h0) | (l0 << 16);
                    pk.y = (uint32_t)__bfloat16_as_ushort(h1) | (l1 << 16);
                    *(uint2*)(g_act + (size_t)slot * NDIM + n) = pk;
                } else {
                    float2 o; o.x = v0 * wtv; o.y = v1 * wtv;
                    *(float2*)(g_y + (size_t)slot * NDIM + n) = o;
                }
            }
        }
    }
}

// ================= combine =================
__global__ void combine_kernel(float* __restrict__ out) {
    int idx = blockIdx.x * 256 + threadIdx.x;
    if (idx >= TOK * (HD/4)) return;
    int t  = idx / (HD/4);
    int h4 = idx % (HD/4);
    int s0 = g_slot_of[t*2+0];
    int s1 = g_slot_of[t*2+1];
    float4 a = *(const float4*)&g_y[(size_t)s0 * HD + h4*4];
    float4 b = *(const float4*)&g_y[(size_t)s1 * HD + h4*4];
    float4 o;
    o.x = a.x + b.x; o.y = a.y + b.y; o.z = a.z + b.z; o.w = a.w + b.w;
    *(float4*)&out[(size_t)t * HD + h4*4] = o;
}

// ================= launch =================
extern "C" void kernel_launch(void* const* d_in, const int* in_sizes, int n_in,
                              void* d_out, int out_size) {
    const float* x  = (const float*)d_in[0];
    const float* Wg = (const float*)d_in[1];
    const float* W1 = (const float*)d_in[2];
    const float* b1 = (const float*)d_in[3];
    const float* W2 = (const float*)d_in[4];
    const float* b2 = (const float*)d_in[5];
    float* out = (float*)d_out;

    __nv_bfloat16 *p_w1h, *p_w1l, *p_w2h, *p_w2l;
    cudaGetSymbolAddress((void**)&p_w1h, g_W1T_hi);
    cudaGetSymbolAddress((void**)&p_w1l, g_W1T_lo);
    cudaGetSymbolAddress((void**)&p_w2h, g_W2T_hi);
    cudaGetSymbolAddress((void**)&p_w2l, g_W2T_lo);

    zero_kernel<<<1, 32>>>();
    transpose_split<HD, FD><<<dim3(FD/32, HD/32, NE), dim3(32, 8)>>>(W1, p_w1h, p_w1l);
    transpose_split<FD, HD><<<dim3(HD/32, FD/32, NE), dim3(32, 8)>>>(W2, p_w2h, p_w2l);
    router_kernel<<<TOK/8, 256>>>(x, Wg);
    scan_kernel<<<1, 1>>>();
    scatter_kernel<<<TOK/256, 256>>>();

    // Pass A: gather(x) @ W1T -> silu -> g_act (packed bf16 hi/lo)
    moe_gemm<HD, FD, true><<<dim3(FD/128, 32, NE), 256>>>(x, p_w1h, p_w1l, b1);
    // Pass B: g_act @ W2T -> *wt -> g_y
    moe_gemm<FD, HD, false><<<dim3(HD/128, 32, NE), 256>>>(nullptr, p_w2h, p_w2l, b2);

    combine_kernel<<<(TOK*(HD/4) + 255)/256, 256>>>(out);
}